// round 15
// baseline (speedup 1.0000x reference)
#include <cuda_runtime.h>
#include <cuda_fp16.h>
#include <math.h>
#include <stdint.h>

#define Bc 4
#define Nn 2048
#define Mm 1024
#define Dd 512
#define Hh 8
#define SCALE 0.125f
#define NEGV -9e15f

// ---------------- scratch (static device memory; no allocations) ------------
#define OFF_QNH   0ULL
#define OFF_KNH   2097152ULL
#define OFF_VTNH  4194304ULL
#define OFF_QEH   6291456ULL
#define OFF_KEH   7340032ULL
#define OFF_VTEH  8388608ULL
#define OFF_EATTN 9437184ULL
#define OFF_ELN   11534336ULL
#define OFF_HID   12582912ULL
#define OFF_PKO   13631488ULL
#define OFF_PKT   13893632ULL
#define OFF_XH    14155776ULL
#define OFF_EH    16252928ULL
#define OFF_WTH   17301504ULL
#define OFF_EOUTH 18350080ULL
#define SCRATCH_FLOATS 19398656ULL

__device__ float g_scratch[SCRATCH_FLOATS];

__device__ __forceinline__ float gelu_exact(float x) {
    return 0.5f * x * (1.0f + erff(x * 0.70710678118654752f));
}

__device__ __forceinline__ uint32_t pkh2(float a, float b) {
    __half2 h = __floats2half2_rn(a, b);
    return *(uint32_t*)&h;
}

__device__ __forceinline__ void mma16(float d[4], const uint32_t a[4],
                                      uint32_t b0, uint32_t b1) {
    asm volatile("mma.sync.aligned.m16n8k16.row.col.f32.f16.f16.f32 "
                 "{%0,%1,%2,%3}, {%4,%5,%6,%7}, {%8,%9}, {%0,%1,%2,%3};"
                 : "+f"(d[0]), "+f"(d[1]), "+f"(d[2]), "+f"(d[3])
                 : "r"(a[0]), "r"(a[1]), "r"(a[2]), "r"(a[3]),
                   "r"(b0), "r"(b1));
}

__device__ __forceinline__ void cp16(uint32_t dst, const void* src) {
    asm volatile("cp.async.cg.shared.global [%0], [%1], 16;" :: "r"(dst), "l"(src));
}
#define CP_COMMIT() asm volatile("cp.async.commit_group;")
#define CP_WAIT(n)  asm volatile("cp.async.wait_group %0;" :: "n"(n))

// ---------------- fp16 pre-conversion (fused X + E) ---------------------------
__global__ __launch_bounds__(256) void conv_h2(const float4* __restrict__ inA,
                                               uint2* __restrict__ outA, int nA,
                                               const float4* __restrict__ inB,
                                               uint2* __restrict__ outB, int nB) {
    int i = blockIdx.x * 256 + threadIdx.x;
    const float4* in = (blockIdx.y == 0) ? inA : inB;
    uint2* out = (blockIdx.y == 0) ? outA : outB;
    int n = (blockIdx.y == 0) ? nA : nB;
    if (i < n) {
        float4 v = in[i];
        out[i] = make_uint2(pkh2(v.x, v.y), pkh2(v.z, v.w));
    }
}

// weights: W[k][n] fp32 -> Wt[n][k] half; 64k x 32n tiles, uint32 stores
struct P4 { const float* p[4]; };
__global__ void conv_wt4(P4 ws, __half* __restrict__ out) {
    __shared__ float t[64][33];
    int g = blockIdx.z;
    int k0 = blockIdx.x * 64, n0 = blockIdx.y * 32;
    const float* W = ws.p[g];
    int tx = threadIdx.x, ty = threadIdx.y;   // 32 x 8
#pragma unroll
    for (int i = 0; i < 8; i++)
        t[ty + 8 * i][tx] = W[(size_t)(k0 + ty + 8 * i) * 512 + n0 + tx];
    __syncthreads();
    uint32_t* o = (uint32_t*)(out + (size_t)g * 262144);
#pragma unroll
    for (int i = 0; i < 4; i++) {
        int row = ty + 8 * i;
        o[(((size_t)(n0 + row) * 512 + k0) >> 1) + tx] =
            pkh2(t[2 * tx][row], t[2 * tx + 1][row]);
    }
}

// ---------------- mask pack + bit transpose -----------------------------------
__global__ __launch_bounds__(256) void pack_mask(const int* __restrict__ inc,
                                                 uint32_t* __restrict__ pk) {
    int w = blockIdx.x * 256 + threadIdx.x;
    int row = w >> 5, mw = w & 31;
    const int4* p = (const int4*)(inc + (size_t)row * Mm + mw * 32);
    uint32_t v = 0;
#pragma unroll
    for (int i = 0; i < 8; i++) {
        int4 q = p[i];
        v |= (q.x > 0 ? 1u : 0u) << (i * 4 + 0);
        v |= (q.y > 0 ? 1u : 0u) << (i * 4 + 1);
        v |= (q.z > 0 ? 1u : 0u) << (i * 4 + 2);
        v |= (q.w > 0 ? 1u : 0u) << (i * 4 + 3);
    }
    pk[w] = v;
}

__global__ __launch_bounds__(256) void transp_bits(const uint32_t* __restrict__ pkO,
                                                   uint32_t* __restrict__ pkT) {
    int gw = (blockIdx.x * 256 + threadIdx.x) >> 5;
    int lane = threadIdx.x & 31;
    int b = gw >> 11;
    int rem = gw & 2047;
    int ng = rem >> 5;
    int mw = rem & 31;
    uint32_t w = pkO[((size_t)b * Nn + ng * 32 + lane) * 32 + mw];
    uint32_t o = 0;
#pragma unroll
    for (int j = 0; j < 32; j++) {
        uint32_t bl = __ballot_sync(0xffffffffu, (w >> j) & 1u);
        if (lane == j) o = bl;
    }
    pkT[((size_t)b * Mm + mw * 32 + lane) * 64 + ng] = o;
}

// ---------------- fp16 GEMM with cp.async pipeline (templated BM) -------------
struct GemmJob {
    const uint32_t* A;
    const uint32_t* W;
    const float*    bias;
    void*           out0;
    void*           out1;
    int act;
    int mode;              // 0 fp32; 2 fp32+half; 3 half; 4 half transposed per head
    int vstride;
    int bshift;
    int nby;
};
struct GemmJobs { GemmJob j[4]; };

#define GEMM_SMEM_128 ((2 * 128 * 36 + 2 * 128 * 36) * 4)
#define GEMM_SMEM_64  ((2 * 64 * 36 + 2 * 128 * 36) * 4)

template <int BM>
__global__ __launch_bounds__(256) void sgemm_h(GemmJobs jobs) {
    const GemmJob J = jobs.j[blockIdx.z];
    if (blockIdx.y >= J.nby) return;

    constexpr int NT = (BM == 128) ? 8 : 4;
    extern __shared__ uint32_t sm[];
    uint32_t* As = sm;
    uint32_t* Ws = sm + 2 * BM * 36;
    uint32_t asAddr = (uint32_t)__cvta_generic_to_shared(As);
    uint32_t wsAddr = (uint32_t)__cvta_generic_to_shared(Ws);

    int tid = threadIdx.x;
    int w = tid >> 5, lane = tid & 31;
    int r = lane >> 2, c = lane & 3;
    int wm = (BM == 128) ? (w & 3) * 32 : (w & 1) * 32;
    int wn = (BM == 128) ? (w >> 2) * 64 : (w >> 1) * 32;
    int row0 = blockIdx.y * BM, col0 = blockIdx.x * 128;

    float acc[2][NT][4];
#pragma unroll
    for (int mi = 0; mi < 2; mi++)
#pragma unroll
        for (int nt = 0; nt < NT; nt++)
#pragma unroll
            for (int j = 0; j < 4; j++) acc[mi][nt][j] = 0.0f;

    auto stage = [&](int buf, int kc) {
        int kt = kc * 32;
#pragma unroll
        for (int i = 0; i < BM / 32; i++) {
            int lin = tid + i * 256;
            int row = lin >> 3, seg = lin & 7;
            cp16(asAddr + (((buf * BM + row) * 36 + seg * 4) << 2),
                 J.A + (size_t)(row0 + row) * 256 + kt + seg * 4);
        }
#pragma unroll
        for (int i = 0; i < 4; i++) {
            int lin = tid + i * 256;
            int row = lin >> 3, seg = lin & 7;
            cp16(wsAddr + (((buf * 128 + row) * 36 + seg * 4) << 2),
                 J.W + (size_t)(col0 + row) * 256 + kt + seg * 4);
        }
    };

    stage(0, 0);
    CP_COMMIT();

    for (int kc = 0; kc < 8; kc++) {
        if (kc + 1 < 8) {
            stage((kc + 1) & 1, kc + 1);
            CP_COMMIT();
            CP_WAIT(1);
        } else {
            CP_WAIT(0);
        }
        __syncthreads();
        const uint32_t* Ab = As + (kc & 1) * BM * 36;
        const uint32_t* Wb = Ws + (kc & 1) * 128 * 36;
#pragma unroll
        for (int ks = 0; ks < 4; ks++) {
            uint32_t a[2][4];
#pragma unroll
            for (int mi = 0; mi < 2; mi++) {
                int mr = wm + mi * 16;
                a[mi][0] = Ab[(mr + r) * 36 + ks * 8 + c];
                a[mi][1] = Ab[(mr + r + 8) * 36 + ks * 8 + c];
                a[mi][2] = Ab[(mr + r) * 36 + ks * 8 + c + 4];
                a[mi][3] = Ab[(mr + r + 8) * 36 + ks * 8 + c + 4];
            }
#pragma unroll
            for (int nt = 0; nt < NT; nt++) {
                uint32_t b0 = Wb[(wn + nt * 8 + r) * 36 + ks * 8 + c];
                uint32_t b1 = Wb[(wn + nt * 8 + r) * 36 + ks * 8 + c + 4];
                mma16(acc[0][nt], a[0], b0, b1);
                mma16(acc[1][nt], a[1], b0, b1);
            }
        }
        __syncthreads();
    }

#pragma unroll
    for (int mi = 0; mi < 2; mi++) {
        int row = row0 + wm + mi * 16 + r;
#pragma unroll
        for (int nt = 0; nt < NT; nt++) {
            int col = col0 + wn + nt * 8 + 2 * c;
            float2 bv = *(const float2*)&J.bias[col];
            float x0 = acc[mi][nt][0] + bv.x, y0 = acc[mi][nt][1] + bv.y;
            float x1 = acc[mi][nt][2] + bv.x, y1 = acc[mi][nt][3] + bv.y;
            if (J.act) {
                x0 = gelu_exact(x0); y0 = gelu_exact(y0);
                x1 = gelu_exact(x1); y1 = gelu_exact(y1);
            }
            if (J.mode == 0 || J.mode == 2) {
                float* C = (float*)J.out0;
                *(float2*)&C[(size_t)row * 512 + col] = make_float2(x0, y0);
                *(float2*)&C[(size_t)(row + 8) * 512 + col] = make_float2(x1, y1);
            }
            if (J.mode == 2) {
                uint32_t* Ch = (uint32_t*)J.out1;
                Ch[((size_t)row * 512 + col) >> 1] = pkh2(x0, y0);
                Ch[((size_t)(row + 8) * 512 + col) >> 1] = pkh2(x1, y1);
            }
            if (J.mode == 3) {
                uint32_t* Ch = (uint32_t*)J.out0;
                Ch[((size_t)row * 512 + col) >> 1] = pkh2(x0, y0);
                Ch[((size_t)(row + 8) * 512 + col) >> 1] = pkh2(x1, y1);
            }
            if (J.mode == 4) {
                __half* VT = (__half*)J.out0;
                int h = col >> 6, dd = col & 63;
                int bb = row >> J.bshift;
                int key = row & ((1 << J.bshift) - 1);
                size_t base = ((size_t)(bb * 8 + h) * 64 + dd) * J.vstride;
                size_t base1 = base + J.vstride;
                VT[base + key]      = __float2half_rn(x0);
                VT[base1 + key]     = __float2half_rn(y0);
                VT[base + key + 8]  = __float2half_rn(x1);
                VT[base1 + key + 8] = __float2half_rn(y1);
            }
        }
    }
}

// ---------------- fp16 flash: register P, h2exp2 softmax, 3-deep KV pipe ------
#define KT_ST 2304   /* 64*36 u32 */
#define QS_ST 4608   /* 128*36 u32 */
#define FLASH_SMEM ((6 * KT_ST + QS_ST) * 4)   /* 73728 B */
#define SC2 0.18033688011112042f               /* SCALE * log2(e) */

__global__ __launch_bounds__(128) void flash_fp16(const __half* __restrict__ Q,
                                                  const __half* __restrict__ K,
                                                  const __half* __restrict__ VT,
                                                  const uint32_t* __restrict__ pk,
                                                  float* __restrict__ Out,
                                                  int L1, int L2) {
    extern __shared__ uint32_t fsm[];
    uint32_t* Kt = fsm;                        // [3][64][36]
    uint32_t* Vt = fsm + 3 * KT_ST;            // [3][64][36]
    uint32_t* Qs = fsm + 6 * KT_ST;            // [128][36] Q resident
    uint32_t ktAddr = (uint32_t)__cvta_generic_to_shared(Kt);
    uint32_t vtAddr = (uint32_t)__cvta_generic_to_shared(Vt);
    uint32_t qsAddr = (uint32_t)__cvta_generic_to_shared(Qs);

    int tid = threadIdx.x;
    int w = tid >> 5, lane = tid & 31;
    int r = lane >> 2, c = lane & 3;
    int w32 = w * 32;
    int bh = blockIdx.y;
    int b = bh >> 3, h = bh & 7;
    int q0 = blockIdx.x * 128;

    const __half* Qb  = Q + ((size_t)b * L1 + q0) * 512 + h * 64;
    const __half* Kb  = K + ((size_t)b * L2) * 512 + h * 64;
    const __half* VTb = VT + ((size_t)(b * 8 + h) * 64) * L2;
    int nw = L2 >> 5;
    const uint32_t* pr[2][2];
#pragma unroll
    for (int mi = 0; mi < 2; mi++) {
        pr[mi][0] = pk + ((size_t)b * L1 + q0 + w32 + mi * 16 + r) * nw;
        pr[mi][1] = pk + ((size_t)b * L1 + q0 + w32 + mi * 16 + r + 8) * nw;
    }

    auto stageKV = [&](int buf, int n0) {
#pragma unroll
        for (int i = 0; i < 4; i++) {
            int lin = tid + i * 128;
            int row = lin >> 3, seg = lin & 7;
            cp16(ktAddr + ((buf * KT_ST + row * 36 + seg * 4) << 2),
                 Kb + (size_t)(n0 + row) * 512 + seg * 8);
        }
#pragma unroll
        for (int i = 0; i < 4; i++) {
            int lin = tid + i * 128;
            int row = lin >> 3, seg = lin & 7;
            cp16(vtAddr + ((buf * KT_ST + row * 36 + seg * 4) << 2),
                 VTb + (size_t)row * L2 + n0 + seg * 8);
        }
    };

    int T = L2 >> 6;
#pragma unroll
    for (int i = 0; i < 8; i++) {
        int lin = tid + i * 128;
        int row = lin >> 3, seg = lin & 7;
        cp16(qsAddr + ((row * 36 + seg * 4) << 2),
             Qb + (size_t)row * 512 + seg * 8);
    }
    stageKV(0, 0);
    CP_COMMIT();
    if (T > 1) {
        stageKV(1, 64);
        CP_COMMIT();
    }

    float o[2][8][4];
#pragma unroll
    for (int mi = 0; mi < 2; mi++)
#pragma unroll
        for (int nt = 0; nt < 8; nt++)
#pragma unroll
            for (int j = 0; j < 4; j++) o[mi][nt][j] = 0.0f;
    float mrow[2][2], lrow[2][2];
#pragma unroll
    for (int mi = 0; mi < 2; mi++) {
        mrow[mi][0] = -INFINITY; mrow[mi][1] = -INFINITY;
        lrow[mi][0] = 0.0f; lrow[mi][1] = 0.0f;
    }

    for (int t = 0; t < T; t++) {
        int n0 = t << 6;
        uint32_t mw[2][2][2];
#pragma unroll
        for (int mi = 0; mi < 2; mi++)
#pragma unroll
            for (int hf = 0; hf < 2; hf++) {
                mw[mi][hf][0] = __ldg(pr[mi][hf] + (n0 >> 5));
                mw[mi][hf][1] = __ldg(pr[mi][hf] + (n0 >> 5) + 1);
            }
        if (t + 1 < T) {
            CP_WAIT(1);
        } else {
            CP_WAIT(0);
        }
        __syncthreads();
        if (t + 2 < T) {
            stageKV((t + 2) % 3, (t + 2) << 6);
            CP_COMMIT();
        }
        const uint32_t* Ktb = Kt + (t % 3) * KT_ST;
        const uint32_t* Vtb = Vt + (t % 3) * KT_ST;

        float s[2][8][4];
#pragma unroll
        for (int mi = 0; mi < 2; mi++)
#pragma unroll
            for (int nt = 0; nt < 8; nt++)
#pragma unroll
                for (int j = 0; j < 4; j++) s[mi][nt][j] = 0.0f;
#pragma unroll
        for (int ks = 0; ks < 4; ks++) {
            uint32_t a[2][4];
#pragma unroll
            for (int mi = 0; mi < 2; mi++) {
                int mr = w32 + mi * 16;
                a[mi][0] = Qs[(mr + r) * 36 + ks * 8 + c];
                a[mi][1] = Qs[(mr + r + 8) * 36 + ks * 8 + c];
                a[mi][2] = Qs[(mr + r) * 36 + ks * 8 + c + 4];
                a[mi][3] = Qs[(mr + r + 8) * 36 + ks * 8 + c + 4];
            }
#pragma unroll
            for (int nt = 0; nt < 8; nt++) {
                uint32_t b0 = Ktb[(nt * 8 + r) * 36 + ks * 8 + c];
                uint32_t b1 = Ktb[(nt * 8 + r) * 36 + ks * 8 + c + 4];
                mma16(s[0][nt], a[0], b0, b1);
                mma16(s[1][nt], a[1], b0, b1);
            }
        }

        // mask (log2 domain) + online softmax; exp2 in packed half2 (h2exp2).
        // pp[mi][nt][0] = exp2 of (row r, cols nt*8+2c,+1), [1] = row r+8.
        uint32_t pp[2][8][2];
#pragma unroll
        for (int mi = 0; mi < 2; mi++) {
#pragma unroll
            for (int nt = 0; nt < 8; nt++) {
                int k0 = nt * 8 + 2 * c;
                uint32_t wr0 = (k0 < 32) ? mw[mi][0][0] : mw[mi][0][1];
                uint32_t wr1 = (k0 < 32) ? mw[mi][1][0] : mw[mi][1][1];
                int sh = k0 & 31;
                s[mi][nt][0] = ((wr0 >> sh) & 1u)       ? s[mi][nt][0] * SC2 : NEGV;
                s[mi][nt][1] = ((wr0 >> (sh + 1)) & 1u) ? s[mi][nt][1] * SC2 : NEGV;
                s[mi][nt][2] = ((wr1 >> sh) & 1u)       ? s[mi][nt][2] * SC2 : NEGV;
                s[mi][nt][3] = ((wr1 >> (sh + 1)) & 1u) ? s[mi][nt][3] * SC2 : NEGV;
            }

            float tm0 = -INFINITY, tm1 = -INFINITY;
#pragma unroll
            for (int nt = 0; nt < 8; nt++) {
                tm0 = fmaxf(tm0, fmaxf(s[mi][nt][0], s[mi][nt][1]));
                tm1 = fmaxf(tm1, fmaxf(s[mi][nt][2], s[mi][nt][3]));
            }
            tm0 = fmaxf(tm0, __shfl_xor_sync(0xffffffffu, tm0, 1));
            tm0 = fmaxf(tm0, __shfl_xor_sync(0xffffffffu, tm0, 2));
            tm1 = fmaxf(tm1, __shfl_xor_sync(0xffffffffu, tm1, 1));
            tm1 = fmaxf(tm1, __shfl_xor_sync(0xffffffffu, tm1, 2));
            float mn0 = fmaxf(mrow[mi][0], tm0), mn1 = fmaxf(mrow[mi][1], tm1);
            float a0 = exp2f(mrow[mi][0] - mn0), a1 = exp2f(mrow[mi][1] - mn1);
            mrow[mi][0] = mn0; mrow[mi][1] = mn1;

            float rs0 = 0.0f, rs1 = 0.0f;
#pragma unroll
            for (int nt = 0; nt < 8; nt++) {
                __half2 d0 = __floats2half2_rn(s[mi][nt][0] - mn0, s[mi][nt][1] - mn0);
                __half2 d1 = __floats2half2_rn(s[mi][nt][2] - mn1, s[mi][nt][3] - mn1);
                __half2 p0 = h2exp2(d0);
                __half2 p1 = h2exp2(d1);
                pp[mi][nt][0] = *(uint32_t*)&p0;
                pp[mi][nt][1] = *(uint32_t*)&p1;
                float2 f0 = __half22float2(p0);
                float2 f1 = __half22float2(p1);
                rs0 += f0.x + f0.y;
                rs1 += f1.x + f1.y;
            }
            rs0 += __shfl_xor_sync(0xffffffffu, rs0, 1);
            rs0 += __shfl_xor_sync(0xffffffffu, rs0, 2);
            rs1 += __shfl_xor_sync(0xffffffffu, rs1, 1);
            rs1 += __shfl_xor_sync(0xffffffffu, rs1, 2);
            lrow[mi][0] = lrow[mi][0] * a0 + rs0;
            lrow[mi][1] = lrow[mi][1] * a1 + rs1;
#pragma unroll
            for (int nt = 0; nt < 8; nt++) {
                o[mi][nt][0] *= a0; o[mi][nt][1] *= a0;
                o[mi][nt][2] *= a1; o[mi][nt][3] *= a1;
            }
        }

#pragma unroll
        for (int kt = 0; kt < 4; kt++) {
            uint32_t pa[2][4];
#pragma unroll
            for (int mi = 0; mi < 2; mi++) {
                pa[mi][0] = pp[mi][2 * kt][0];
                pa[mi][1] = pp[mi][2 * kt][1];
                pa[mi][2] = pp[mi][2 * kt + 1][0];
                pa[mi][3] = pp[mi][2 * kt + 1][1];
            }
#pragma unroll
            for (int nt = 0; nt < 8; nt++) {
                uint32_t b0 = Vtb[(nt * 8 + r) * 36 + kt * 8 + c];
                uint32_t b1 = Vtb[(nt * 8 + r) * 36 + kt * 8 + c + 4];
                mma16(o[0][nt], pa[0], b0, b1);
                mma16(o[1][nt], pa[1], b0, b1);
            }
        }
    }

    float* Ob = Out + ((size_t)b * L1 + q0) * 512 + h * 64;
#pragma unroll
    for (int mi = 0; mi < 2; mi++) {
        float inv0 = 1.0f / lrow[mi][0], inv1 = 1.0f / lrow[mi][1];
        int mr = w32 + mi * 16;
#pragma unroll
        for (int nt = 0; nt < 8; nt++) {
            int col = nt * 8 + 2 * c;
            float2 v0, v1;
            v0.x = gelu_exact(o[mi][nt][0] * inv0);
            v0.y = gelu_exact(o[mi][nt][1] * inv0);
            v1.x = gelu_exact(o[mi][nt][2] * inv1);
            v1.y = gelu_exact(o[mi][nt][3] * inv1);
            *(float2*)(Ob + (size_t)(mr + r) * 512 + col) = v0;
            *(float2*)(Ob + (size_t)(mr + r + 8) * 512 + col) = v1;
        }
    }
}

// ---------------- layernorm(E + A) -> half ------------------------------------
__global__ __launch_bounds__(256) void ln_residual(const float* __restrict__ E,
                                                   const float* __restrict__ A,
                                                   const float* __restrict__ g,
                                                   const float* __restrict__ bb,
                                                   uint32_t* __restrict__ Out) {
    __shared__ float s1[256], s2[256];
    int tid = threadIdx.x;
    size_t base = (size_t)blockIdx.x * 512;
    float2 e = *(const float2*)&E[base + 2 * tid];
    float2 a = *(const float2*)&A[base + 2 * tid];
    float x0 = e.x + a.x, x1 = e.y + a.y;
    s1[tid] = x0 + x1;
    s2[tid] = x0 * x0 + x1 * x1;
    __syncthreads();
    for (int s = 128; s > 0; s >>= 1) {
        if (tid < s) { s1[tid] += s1[tid + s]; s2[tid] += s2[tid + s]; }
        __syncthreads();
    }
    float mu  = s1[0] * (1.0f / 512.0f);
    float var = s2[0] * (1.0f / 512.0f) - mu * mu;
    float inv = rsqrtf(var + 1e-7f);
    float2 gg = *(const float2*)&g[2 * tid];
    float2 bv = *(const float2*)&bb[2 * tid];
    Out[(base >> 1) + tid] = pkh2((x0 - mu) * inv * gg.x + bv.x,
                                  (x1 - mu) * inv * gg.y + bv.y);
}

// =============================================================================
extern "C" void kernel_launch(void* const* d_in, const int* in_sizes, int n_in,
                              void* d_out, int out_size) {
    const float* X    = (const float*)d_in[0];
    const int*   inc  = (const int*)d_in[1];
    const float* E    = (const float*)d_in[3];
    const float* Wqn  = (const float*)d_in[4];   const float* bqn = (const float*)d_in[5];
    const float* Wkn  = (const float*)d_in[6];   const float* bkn = (const float*)d_in[7];
    const float* Wvn  = (const float*)d_in[8];   const float* bvn = (const float*)d_in[9];
    const float* Wqe  = (const float*)d_in[10];  const float* bqe = (const float*)d_in[11];
    const float* Wke  = (const float*)d_in[12];  const float* bke = (const float*)d_in[13];
    const float* Wve  = (const float*)d_in[14];  const float* bve = (const float*)d_in[15];
    const float* Wm1  = (const float*)d_in[16];  const float* bm1 = (const float*)d_in[17];
    const float* Wm2  = (const float*)d_in[18];  const float* bm2 = (const float*)d_in[19];
    const float* g_ln = (const float*)d_in[20];  const float* b_ln = (const float*)d_in[21];

    float* out  = (float*)d_out;
    float* Xout = out;
    float* Eout = out + (size_t)Bc * Nn * Dd;

    float* sc = nullptr;
    cudaGetSymbolAddress((void**)&sc, g_scratch);
    __half*   QnH   = (__half*)(sc + OFF_QNH);
    __half*   KnH   = (__half*)(sc + OFF_KNH);
    __half*   VTnH  = (__half*)(sc + OFF_VTNH);
    __half*   QeH   = (__half*)(sc + OFF_QEH);
    __half*   KeH   = (__half*)(sc + OFF_KEH);
    __half*   VTeH  = (__half*)(sc + OFF_VTEH);
    float*    Eattn = sc + OFF_EATTN;
    uint32_t* Eln   = (uint32_t*)(sc + OFF_ELN);
    uint32_t* Hid   = (uint32_t*)(sc + OFF_HID);
    uint32_t* pkO   = (uint32_t*)(sc + OFF_PKO);
    uint32_t* pkT   = (uint32_t*)(sc + OFF_PKT);
    uint32_t* Xh    = (uint32_t*)(sc + OFF_XH);
    uint32_t* Eh    = (uint32_t*)(sc + OFF_EH);
    __half*   Wt    = (__half*)(sc + OFF_WTH);
    uint32_t* Wtu   = (uint32_t*)(sc + OFF_WTH);
    uint32_t* EoutH = (uint32_t*)(sc + OFF_EOUTH);

    static cudaStream_t sB = nullptr;
    static cudaEvent_t evFork = nullptr, evJoinA = nullptr, evJoin = nullptr;
    static int attr_set = 0;
    if (!attr_set) {
        cudaFuncSetAttribute(flash_fp16, cudaFuncAttributeMaxDynamicSharedMemorySize,
                             FLASH_SMEM);
        cudaFuncSetAttribute(sgemm_h<128>, cudaFuncAttributeMaxDynamicSharedMemorySize,
                             GEMM_SMEM_128);
        cudaFuncSetAttribute(sgemm_h<64>, cudaFuncAttributeMaxDynamicSharedMemorySize,
                             GEMM_SMEM_64);
        cudaStreamCreateWithFlags(&sB, cudaStreamNonBlocking);
        cudaEventCreateWithFlags(&evFork, cudaEventDisableTiming);
        cudaEventCreateWithFlags(&evJoinA, cudaEventDisableTiming);
        cudaEventCreateWithFlags(&evJoin, cudaEventDisableTiming);
        attr_set = 1;
    }

    // ---- fork: QKV weight conversion first (needed soonest), then masks ----
    cudaEventRecord(evFork, 0);
    cudaStreamWaitEvent(sB, evFork, 0);
    P4 wpA; wpA.p[0] = Wqn; wpA.p[1] = Wkn; wpA.p[2] = Wvn; wpA.p[3] = Wqe;
    conv_wt4<<<dim3(8, 16, 4), dim3(32, 8), 0, sB>>>(wpA, Wt);
    cudaEventRecord(evJoinA, sB);
    pack_mask<<<(Bc * Nn * (Mm / 32)) / 256, 256, 0, sB>>>(inc, pkO);
    transp_bits<<<1024, 256, 0, sB>>>(pkO, pkT);
    P4 wpB; wpB.p[0] = Wke; wpB.p[1] = Wve; wpB.p[2] = Wm1; wpB.p[3] = Wm2;
    conv_wt4<<<dim3(8, 16, 4), dim3(32, 8), 0, sB>>>(wpB, Wt + 4 * 262144);
    cudaEventRecord(evJoin, sB);

    // ---- main stream: activation conversion (parallel with weight conv) ----
    conv_h2<<<dim3(4096, 2), 256>>>((const float4*)X, (uint2*)Xh, 1048576,
                                    (const float4*)E, (uint2*)Eh, 524288);
    cudaStreamWaitEvent(0, evJoinA, 0);

    GemmJobs jobs;
    jobs.j[0] = { Xh, Wtu + 0 * 131072, bqn, QnH,  nullptr, 0, 3, 0, 0, 64 };
    jobs.j[1] = { Xh, Wtu + 1 * 131072, bkn, KnH,  nullptr, 0, 3, 0, 0, 64 };
    jobs.j[2] = { Xh, Wtu + 2 * 131072, bvn, VTnH, nullptr, 0, 4, Nn, 11, 64 };
    jobs.j[3] = { Eh, Wtu + 3 * 131072, bqe, QeH,  nullptr, 0, 3, 0, 0, 32 };
    sgemm_h<128><<<dim3(4, 64, 4), 256, GEMM_SMEM_128>>>(jobs);

    // ---- join: masks + late weights must be ready ----
    cudaStreamWaitEvent(0, evJoin, 0);

    // stage 1: edges attend over nodes
    flash_fp16<<<dim3(Mm / 128, Bc * Hh), 128, FLASH_SMEM>>>(QeH, KnH, VTnH, pkT,
                                                             Eattn, Mm, Nn);

    // residual layernorm + MLP
    ln_residual<<<Bc * Mm, 256>>>(E, Eattn, g_ln, b_ln, Eln);
    jobs.j[0] = { Eln, Wtu + 6 * 131072, bm1, Hid, nullptr, 1, 3, 0, 0, 64 };
    jobs.j[1] = jobs.j[0]; jobs.j[2] = jobs.j[0]; jobs.j[3] = jobs.j[0];
    sgemm_h<64><<<dim3(4, 64, 1), 256, GEMM_SMEM_64>>>(jobs);
    jobs.j[0] = { Hid, Wtu + 7 * 131072, bm2, Eout, EoutH, 0, 2, 0, 0, 64 };
    jobs.j[1] = jobs.j[0]; jobs.j[2] = jobs.j[0]; jobs.j[3] = jobs.j[0];
    sgemm_h<64><<<dim3(4, 64, 1), 256, GEMM_SMEM_64>>>(jobs);

    // edge K/V projections from E_
    jobs.j[0] = { EoutH, Wtu + 4 * 131072, bke, KeH,  nullptr, 0, 3, 0, 0, 64 };
    jobs.j[1] = { EoutH, Wtu + 5 * 131072, bve, VTeH, nullptr, 0, 4, Mm, 10, 64 };
    jobs.j[2] = jobs.j[0]; jobs.j[3] = jobs.j[0];
    sgemm_h<64><<<dim3(4, 64, 2), 256, GEMM_SMEM_64>>>(jobs);

    // stage 2: nodes attend over edges
    flash_fp16<<<dim3(Nn / 128, Bc * Hh), 128, FLASH_SMEM>>>(QnH, KeH, VTeH, pkO,
                                                             Xout, Nn, Mm);
}

// round 16
// speedup vs baseline: 1.0430x; 1.0430x over previous
#include <cuda_runtime.h>
#include <cuda_fp16.h>
#include <math.h>
#include <stdint.h>

#define Bc 4
#define Nn 2048
#define Mm 1024
#define Dd 512
#define Hh 8
#define SCALE 0.125f
#define NEGV -9e15f

// ---------------- scratch (static device memory; no allocations) ------------
#define OFF_QNH   0ULL
#define OFF_KNH   2097152ULL
#define OFF_VTNH  4194304ULL
#define OFF_QEH   6291456ULL
#define OFF_KEH   7340032ULL
#define OFF_VTEH  8388608ULL
#define OFF_EATTN 9437184ULL
#define OFF_ELN   11534336ULL
#define OFF_HID   12582912ULL
#define OFF_PKO   13631488ULL
#define OFF_PKT   13893632ULL
#define OFF_XH    14155776ULL
#define OFF_EH    16252928ULL
#define OFF_WTH   17301504ULL
#define OFF_EOUTH 18350080ULL
#define SCRATCH_FLOATS 19398656ULL

__device__ float g_scratch[SCRATCH_FLOATS];

__device__ __forceinline__ float gelu_exact(float x) {
    return 0.5f * x * (1.0f + erff(x * 0.70710678118654752f));
}

__device__ __forceinline__ uint32_t pkh2(float a, float b) {
    __half2 h = __floats2half2_rn(a, b);
    return *(uint32_t*)&h;
}

__device__ __forceinline__ void mma16(float d[4], const uint32_t a[4],
                                      uint32_t b0, uint32_t b1) {
    asm volatile("mma.sync.aligned.m16n8k16.row.col.f32.f16.f16.f32 "
                 "{%0,%1,%2,%3}, {%4,%5,%6,%7}, {%8,%9}, {%0,%1,%2,%3};"
                 : "+f"(d[0]), "+f"(d[1]), "+f"(d[2]), "+f"(d[3])
                 : "r"(a[0]), "r"(a[1]), "r"(a[2]), "r"(a[3]),
                   "r"(b0), "r"(b1));
}

__device__ __forceinline__ void ldsm4(uint32_t addr, uint32_t& x, uint32_t& y,
                                      uint32_t& z, uint32_t& w) {
    asm volatile("ldmatrix.sync.aligned.m8n8.x4.shared.b16 {%0,%1,%2,%3}, [%4];"
                 : "=r"(x), "=r"(y), "=r"(z), "=r"(w) : "r"(addr));
}

__device__ __forceinline__ void cp16(uint32_t dst, const void* src) {
    asm volatile("cp.async.cg.shared.global [%0], [%1], 16;" :: "r"(dst), "l"(src));
}
#define CP_COMMIT() asm volatile("cp.async.commit_group;")
#define CP_WAIT(n)  asm volatile("cp.async.wait_group %0;" :: "n"(n))

// ---------------- fp16 pre-conversion (fused X + E) ---------------------------
__global__ __launch_bounds__(256) void conv_h2(const float4* __restrict__ inA,
                                               uint2* __restrict__ outA, int nA,
                                               const float4* __restrict__ inB,
                                               uint2* __restrict__ outB, int nB) {
    int i = blockIdx.x * 256 + threadIdx.x;
    const float4* in = (blockIdx.y == 0) ? inA : inB;
    uint2* out = (blockIdx.y == 0) ? outA : outB;
    int n = (blockIdx.y == 0) ? nA : nB;
    if (i < n) {
        float4 v = in[i];
        out[i] = make_uint2(pkh2(v.x, v.y), pkh2(v.z, v.w));
    }
}

// weights: W[k][n] fp32 -> Wt[n][k] half; 64k x 32n tiles, uint32 stores
struct P4 { const float* p[4]; };
__global__ void conv_wt4(P4 ws, __half* __restrict__ out) {
    __shared__ float t[64][33];
    int g = blockIdx.z;
    int k0 = blockIdx.x * 64, n0 = blockIdx.y * 32;
    const float* W = ws.p[g];
    int tx = threadIdx.x, ty = threadIdx.y;   // 32 x 8
#pragma unroll
    for (int i = 0; i < 8; i++)
        t[ty + 8 * i][tx] = W[(size_t)(k0 + ty + 8 * i) * 512 + n0 + tx];
    __syncthreads();
    uint32_t* o = (uint32_t*)(out + (size_t)g * 262144);
#pragma unroll
    for (int i = 0; i < 4; i++) {
        int row = ty + 8 * i;
        o[(((size_t)(n0 + row) * 512 + k0) >> 1) + tx] =
            pkh2(t[2 * tx][row], t[2 * tx + 1][row]);
    }
}

// ---------------- mask pack + bit transpose -----------------------------------
__global__ __launch_bounds__(256) void pack_mask(const int* __restrict__ inc,
                                                 uint32_t* __restrict__ pk) {
    int w = blockIdx.x * 256 + threadIdx.x;
    int row = w >> 5, mw = w & 31;
    const int4* p = (const int4*)(inc + (size_t)row * Mm + mw * 32);
    uint32_t v = 0;
#pragma unroll
    for (int i = 0; i < 8; i++) {
        int4 q = p[i];
        v |= (q.x > 0 ? 1u : 0u) << (i * 4 + 0);
        v |= (q.y > 0 ? 1u : 0u) << (i * 4 + 1);
        v |= (q.z > 0 ? 1u : 0u) << (i * 4 + 2);
        v |= (q.w > 0 ? 1u : 0u) << (i * 4 + 3);
    }
    pk[w] = v;
}

__global__ __launch_bounds__(256) void transp_bits(const uint32_t* __restrict__ pkO,
                                                   uint32_t* __restrict__ pkT) {
    int gw = (blockIdx.x * 256 + threadIdx.x) >> 5;
    int lane = threadIdx.x & 31;
    int b = gw >> 11;
    int rem = gw & 2047;
    int ng = rem >> 5;
    int mw = rem & 31;
    uint32_t w = pkO[((size_t)b * Nn + ng * 32 + lane) * 32 + mw];
    uint32_t o = 0;
#pragma unroll
    for (int j = 0; j < 32; j++) {
        uint32_t bl = __ballot_sync(0xffffffffu, (w >> j) & 1u);
        if (lane == j) o = bl;
    }
    pkT[((size_t)b * Mm + mw * 32 + lane) * 64 + ng] = o;
}

// ---------------- fp16 GEMM with cp.async pipeline (templated BM) -------------
struct GemmJob {
    const uint32_t* A;
    const uint32_t* W;
    const float*    bias;
    void*           out0;
    void*           out1;
    int act;
    int mode;              // 0 fp32; 2 fp32+half; 3 half; 4 half transposed per head
    int vstride;
    int bshift;
    int nby;
};
struct GemmJobs { GemmJob j[4]; };

#define GEMM_SMEM_128 ((2 * 128 * 36 + 2 * 128 * 36) * 4)
#define GEMM_SMEM_64  ((2 * 64 * 36 + 2 * 128 * 36) * 4)

template <int BM>
__global__ __launch_bounds__(256) void sgemm_h(GemmJobs jobs) {
    const GemmJob J = jobs.j[blockIdx.z];
    if (blockIdx.y >= J.nby) return;

    constexpr int NT = (BM == 128) ? 8 : 4;
    extern __shared__ uint32_t sm[];
    uint32_t* As = sm;
    uint32_t* Ws = sm + 2 * BM * 36;
    uint32_t asAddr = (uint32_t)__cvta_generic_to_shared(As);
    uint32_t wsAddr = (uint32_t)__cvta_generic_to_shared(Ws);

    int tid = threadIdx.x;
    int w = tid >> 5, lane = tid & 31;
    int r = lane >> 2, c = lane & 3;
    int wm = (BM == 128) ? (w & 3) * 32 : (w & 1) * 32;
    int wn = (BM == 128) ? (w >> 2) * 64 : (w >> 1) * 32;
    int row0 = blockIdx.y * BM, col0 = blockIdx.x * 128;

    float acc[2][NT][4];
#pragma unroll
    for (int mi = 0; mi < 2; mi++)
#pragma unroll
        for (int nt = 0; nt < NT; nt++)
#pragma unroll
            for (int j = 0; j < 4; j++) acc[mi][nt][j] = 0.0f;

    auto stage = [&](int buf, int kc) {
        int kt = kc * 32;
#pragma unroll
        for (int i = 0; i < BM / 32; i++) {
            int lin = tid + i * 256;
            int row = lin >> 3, seg = lin & 7;
            cp16(asAddr + (((buf * BM + row) * 36 + seg * 4) << 2),
                 J.A + (size_t)(row0 + row) * 256 + kt + seg * 4);
        }
#pragma unroll
        for (int i = 0; i < 4; i++) {
            int lin = tid + i * 256;
            int row = lin >> 3, seg = lin & 7;
            cp16(wsAddr + (((buf * 128 + row) * 36 + seg * 4) << 2),
                 J.W + (size_t)(col0 + row) * 256 + kt + seg * 4);
        }
    };

    stage(0, 0);
    CP_COMMIT();

    for (int kc = 0; kc < 8; kc++) {
        if (kc + 1 < 8) {
            stage((kc + 1) & 1, kc + 1);
            CP_COMMIT();
            CP_WAIT(1);
        } else {
            CP_WAIT(0);
        }
        __syncthreads();
        const uint32_t* Ab = As + (kc & 1) * BM * 36;
        const uint32_t* Wb = Ws + (kc & 1) * 128 * 36;
#pragma unroll
        for (int ks = 0; ks < 4; ks++) {
            uint32_t a[2][4];
#pragma unroll
            for (int mi = 0; mi < 2; mi++) {
                int mr = wm + mi * 16;
                a[mi][0] = Ab[(mr + r) * 36 + ks * 8 + c];
                a[mi][1] = Ab[(mr + r + 8) * 36 + ks * 8 + c];
                a[mi][2] = Ab[(mr + r) * 36 + ks * 8 + c + 4];
                a[mi][3] = Ab[(mr + r + 8) * 36 + ks * 8 + c + 4];
            }
#pragma unroll
            for (int nt = 0; nt < NT; nt++) {
                uint32_t b0 = Wb[(wn + nt * 8 + r) * 36 + ks * 8 + c];
                uint32_t b1 = Wb[(wn + nt * 8 + r) * 36 + ks * 8 + c + 4];
                mma16(acc[0][nt], a[0], b0, b1);
                mma16(acc[1][nt], a[1], b0, b1);
            }
        }
        __syncthreads();
    }

#pragma unroll
    for (int mi = 0; mi < 2; mi++) {
        int row = row0 + wm + mi * 16 + r;
#pragma unroll
        for (int nt = 0; nt < NT; nt++) {
            int col = col0 + wn + nt * 8 + 2 * c;
            float2 bv = *(const float2*)&J.bias[col];
            float x0 = acc[mi][nt][0] + bv.x, y0 = acc[mi][nt][1] + bv.y;
            float x1 = acc[mi][nt][2] + bv.x, y1 = acc[mi][nt][3] + bv.y;
            if (J.act) {
                x0 = gelu_exact(x0); y0 = gelu_exact(y0);
                x1 = gelu_exact(x1); y1 = gelu_exact(y1);
            }
            if (J.mode == 0 || J.mode == 2) {
                float* C = (float*)J.out0;
                *(float2*)&C[(size_t)row * 512 + col] = make_float2(x0, y0);
                *(float2*)&C[(size_t)(row + 8) * 512 + col] = make_float2(x1, y1);
            }
            if (J.mode == 2) {
                uint32_t* Ch = (uint32_t*)J.out1;
                Ch[((size_t)row * 512 + col) >> 1] = pkh2(x0, y0);
                Ch[((size_t)(row + 8) * 512 + col) >> 1] = pkh2(x1, y1);
            }
            if (J.mode == 3) {
                uint32_t* Ch = (uint32_t*)J.out0;
                Ch[((size_t)row * 512 + col) >> 1] = pkh2(x0, y0);
                Ch[((size_t)(row + 8) * 512 + col) >> 1] = pkh2(x1, y1);
            }
            if (J.mode == 4) {
                __half* VT = (__half*)J.out0;
                int h = col >> 6, dd = col & 63;
                int bb = row >> J.bshift;
                int key = row & ((1 << J.bshift) - 1);
                size_t base = ((size_t)(bb * 8 + h) * 64 + dd) * J.vstride;
                size_t base1 = base + J.vstride;
                VT[base + key]      = __float2half_rn(x0);
                VT[base1 + key]     = __float2half_rn(y0);
                VT[base + key + 8]  = __float2half_rn(x1);
                VT[base1 + key + 8] = __float2half_rn(y1);
            }
        }
    }
}

// ---------------- fp16 flash: register P, ldmatrix K/V, 3-deep KV pipe --------
#define KT_ST 2304   /* 64*36 u32 */
#define QS_ST 4608   /* 128*36 u32 */
#define FLASH_SMEM ((6 * KT_ST + QS_ST) * 4)   /* 73728 B */
#define SC2 0.18033688011112042f               /* SCALE * log2(e) */

__global__ __launch_bounds__(128) void flash_fp16(const __half* __restrict__ Q,
                                                  const __half* __restrict__ K,
                                                  const __half* __restrict__ VT,
                                                  const uint32_t* __restrict__ pk,
                                                  float* __restrict__ Out,
                                                  int L1, int L2) {
    extern __shared__ uint32_t fsm[];
    uint32_t* Kt = fsm;                        // [3][64][36]
    uint32_t* Vt = fsm + 3 * KT_ST;            // [3][64][36]
    uint32_t* Qs = fsm + 6 * KT_ST;            // [128][36] Q resident
    uint32_t ktAddr = (uint32_t)__cvta_generic_to_shared(Kt);
    uint32_t vtAddr = (uint32_t)__cvta_generic_to_shared(Vt);
    uint32_t qsAddr = (uint32_t)__cvta_generic_to_shared(Qs);

    int tid = threadIdx.x;
    int w = tid >> 5, lane = tid & 31;
    int r = lane >> 2, c = lane & 3;
    int w32 = w * 32;
    int bh = blockIdx.y;
    int b = bh >> 3, h = bh & 7;
    int q0 = blockIdx.x * 128;

    // ldmatrix per-lane source offset (u32 units within a 64x36 tile):
    // lanes 0-7: nt-even rows, k-lo; 8-15: nt-even, k-hi; 16-23: nt-odd, k-lo;
    // 24-31: nt-odd, k-hi.  addr = base + (soff + ntp*16*36 + ks*8)*4
    int soff = (((lane & 16) ? 8 : 0) + (lane & 7)) * 36 + ((lane & 8) ? 4 : 0);

    const __half* Qb  = Q + ((size_t)b * L1 + q0) * 512 + h * 64;
    const __half* Kb  = K + ((size_t)b * L2) * 512 + h * 64;
    const __half* VTb = VT + ((size_t)(b * 8 + h) * 64) * L2;
    int nw = L2 >> 5;
    const uint32_t* pr[2][2];
#pragma unroll
    for (int mi = 0; mi < 2; mi++) {
        pr[mi][0] = pk + ((size_t)b * L1 + q0 + w32 + mi * 16 + r) * nw;
        pr[mi][1] = pk + ((size_t)b * L1 + q0 + w32 + mi * 16 + r + 8) * nw;
    }

    auto stageKV = [&](int buf, int n0) {
#pragma unroll
        for (int i = 0; i < 4; i++) {
            int lin = tid + i * 128;
            int row = lin >> 3, seg = lin & 7;
            cp16(ktAddr + ((buf * KT_ST + row * 36 + seg * 4) << 2),
                 Kb + (size_t)(n0 + row) * 512 + seg * 8);
        }
#pragma unroll
        for (int i = 0; i < 4; i++) {
            int lin = tid + i * 128;
            int row = lin >> 3, seg = lin & 7;
            cp16(vtAddr + ((buf * KT_ST + row * 36 + seg * 4) << 2),
                 VTb + (size_t)row * L2 + n0 + seg * 8);
        }
    };

    int T = L2 >> 6;
#pragma unroll
    for (int i = 0; i < 8; i++) {
        int lin = tid + i * 128;
        int row = lin >> 3, seg = lin & 7;
        cp16(qsAddr + ((row * 36 + seg * 4) << 2),
             Qb + (size_t)row * 512 + seg * 8);
    }
    stageKV(0, 0);
    CP_COMMIT();
    if (T > 1) {
        stageKV(1, 64);
        CP_COMMIT();
    }

    float o[2][8][4];
#pragma unroll
    for (int mi = 0; mi < 2; mi++)
#pragma unroll
        for (int nt = 0; nt < 8; nt++)
#pragma unroll
            for (int j = 0; j < 4; j++) o[mi][nt][j] = 0.0f;
    float mrow[2][2], lrow[2][2];
#pragma unroll
    for (int mi = 0; mi < 2; mi++) {
        mrow[mi][0] = -INFINITY; mrow[mi][1] = -INFINITY;
        lrow[mi][0] = 0.0f; lrow[mi][1] = 0.0f;
    }

    for (int t = 0; t < T; t++) {
        int n0 = t << 6;
        uint32_t mw[2][2][2];
#pragma unroll
        for (int mi = 0; mi < 2; mi++)
#pragma unroll
            for (int hf = 0; hf < 2; hf++) {
                mw[mi][hf][0] = __ldg(pr[mi][hf] + (n0 >> 5));
                mw[mi][hf][1] = __ldg(pr[mi][hf] + (n0 >> 5) + 1);
            }
        if (t + 1 < T) {
            CP_WAIT(1);
        } else {
            CP_WAIT(0);
        }
        __syncthreads();
        if (t + 2 < T) {
            stageKV((t + 2) % 3, (t + 2) << 6);
            CP_COMMIT();
        }
        uint32_t ktb = ktAddr + (((t % 3) * KT_ST + soff) << 2);
        uint32_t vtb = vtAddr + (((t % 3) * KT_ST + soff) << 2);

        // S = Q @ K^T : A from resident Qs (scalar), B via ldmatrix.x4
        float s[2][8][4];
#pragma unroll
        for (int mi = 0; mi < 2; mi++)
#pragma unroll
            for (int nt = 0; nt < 8; nt++)
#pragma unroll
                for (int j = 0; j < 4; j++) s[mi][nt][j] = 0.0f;
#pragma unroll
        for (int ks = 0; ks < 4; ks++) {
            uint32_t a[2][4];
#pragma unroll
            for (int mi = 0; mi < 2; mi++) {
                int mr = w32 + mi * 16;
                a[mi][0] = Qs[(mr + r) * 36 + ks * 8 + c];
                a[mi][1] = Qs[(mr + r + 8) * 36 + ks * 8 + c];
                a[mi][2] = Qs[(mr + r) * 36 + ks * 8 + c + 4];
                a[mi][3] = Qs[(mr + r + 8) * 36 + ks * 8 + c + 4];
            }
#pragma unroll
            for (int ntp = 0; ntp < 4; ntp++) {
                uint32_t b0e, b1e, b0o, b1o;
                ldsm4(ktb + ((ntp * 576 + ks * 8) << 2), b0e, b1e, b0o, b1o);
                mma16(s[0][2 * ntp],     a[0], b0e, b1e);
                mma16(s[1][2 * ntp],     a[1], b0e, b1e);
                mma16(s[0][2 * ntp + 1], a[0], b0o, b1o);
                mma16(s[1][2 * ntp + 1], a[1], b0o, b1o);
            }
        }

        // mask (log2 domain) + online softmax; P packed into registers
        uint32_t pp[2][8][2];
#pragma unroll
        for (int mi = 0; mi < 2; mi++) {
#pragma unroll
            for (int nt = 0; nt < 8; nt++) {
                int k0 = nt * 8 + 2 * c;
                uint32_t wr0 = (k0 < 32) ? mw[mi][0][0] : mw[mi][0][1];
                uint32_t wr1 = (k0 < 32) ? mw[mi][1][0] : mw[mi][1][1];
                int sh = k0 & 31;
                s[mi][nt][0] = ((wr0 >> sh) & 1u)       ? s[mi][nt][0] * SC2 : NEGV;
                s[mi][nt][1] = ((wr0 >> (sh + 1)) & 1u) ? s[mi][nt][1] * SC2 : NEGV;
                s[mi][nt][2] = ((wr1 >> sh) & 1u)       ? s[mi][nt][2] * SC2 : NEGV;
                s[mi][nt][3] = ((wr1 >> (sh + 1)) & 1u) ? s[mi][nt][3] * SC2 : NEGV;
            }

            float tm0 = -INFINITY, tm1 = -INFINITY;
#pragma unroll
            for (int nt = 0; nt < 8; nt++) {
                tm0 = fmaxf(tm0, fmaxf(s[mi][nt][0], s[mi][nt][1]));
                tm1 = fmaxf(tm1, fmaxf(s[mi][nt][2], s[mi][nt][3]));
            }
            tm0 = fmaxf(tm0, __shfl_xor_sync(0xffffffffu, tm0, 1));
            tm0 = fmaxf(tm0, __shfl_xor_sync(0xffffffffu, tm0, 2));
            tm1 = fmaxf(tm1, __shfl_xor_sync(0xffffffffu, tm1, 1));
            tm1 = fmaxf(tm1, __shfl_xor_sync(0xffffffffu, tm1, 2));
            float mn0 = fmaxf(mrow[mi][0], tm0), mn1 = fmaxf(mrow[mi][1], tm1);
            float a0 = exp2f(mrow[mi][0] - mn0), a1 = exp2f(mrow[mi][1] - mn1);
            mrow[mi][0] = mn0; mrow[mi][1] = mn1;

            float rs0 = 0.0f, rs1 = 0.0f;
#pragma unroll
            for (int nt = 0; nt < 8; nt++) {
                float p0 = exp2f(s[mi][nt][0] - mn0);
                float p1 = exp2f(s[mi][nt][1] - mn0);
                float p2 = exp2f(s[mi][nt][2] - mn1);
                float p3 = exp2f(s[mi][nt][3] - mn1);
                rs0 += p0 + p1; rs1 += p2 + p3;
                pp[mi][nt][0] = pkh2(p0, p1);
                pp[mi][nt][1] = pkh2(p2, p3);
            }
            rs0 += __shfl_xor_sync(0xffffffffu, rs0, 1);
            rs0 += __shfl_xor_sync(0xffffffffu, rs0, 2);
            rs1 += __shfl_xor_sync(0xffffffffu, rs1, 1);
            rs1 += __shfl_xor_sync(0xffffffffu, rs1, 2);
            lrow[mi][0] = lrow[mi][0] * a0 + rs0;
            lrow[mi][1] = lrow[mi][1] * a1 + rs1;
#pragma unroll
            for (int nt = 0; nt < 8; nt++) {
                o[mi][nt][0] *= a0; o[mi][nt][1] *= a0;
                o[mi][nt][2] *= a1; o[mi][nt][3] *= a1;
            }
        }

        // O += P @ V : P from registers, V via ldmatrix.x4
#pragma unroll
        for (int kt = 0; kt < 4; kt++) {
            uint32_t pa[2][4];
#pragma unroll
            for (int mi = 0; mi < 2; mi++) {
                pa[mi][0] = pp[mi][2 * kt][0];
                pa[mi][1] = pp[mi][2 * kt][1];
                pa[mi][2] = pp[mi][2 * kt + 1][0];
                pa[mi][3] = pp[mi][2 * kt + 1][1];
            }
#pragma unroll
            for (int ntp = 0; ntp < 4; ntp++) {
                uint32_t b0e, b1e, b0o, b1o;
                ldsm4(vtb + ((ntp * 576 + kt * 8) << 2), b0e, b1e, b0o, b1o);
                mma16(o[0][2 * ntp],     pa[0], b0e, b1e);
                mma16(o[1][2 * ntp],     pa[1], b0e, b1e);
                mma16(o[0][2 * ntp + 1], pa[0], b0o, b1o);
                mma16(o[1][2 * ntp + 1], pa[1], b0o, b1o);
            }
        }
    }

    float* Ob = Out + ((size_t)b * L1 + q0) * 512 + h * 64;
#pragma unroll
    for (int mi = 0; mi < 2; mi++) {
        float inv0 = 1.0f / lrow[mi][0], inv1 = 1.0f / lrow[mi][1];
        int mr = w32 + mi * 16;
#pragma unroll
        for (int nt = 0; nt < 8; nt++) {
            int col = nt * 8 + 2 * c;
            float2 v0, v1;
            v0.x = gelu_exact(o[mi][nt][0] * inv0);
            v0.y = gelu_exact(o[mi][nt][1] * inv0);
            v1.x = gelu_exact(o[mi][nt][2] * inv1);
            v1.y = gelu_exact(o[mi][nt][3] * inv1);
            *(float2*)(Ob + (size_t)(mr + r) * 512 + col) = v0;
            *(float2*)(Ob + (size_t)(mr + r + 8) * 512 + col) = v1;
        }
    }
}

// ---------------- layernorm(E + A) -> half ------------------------------------
__global__ __launch_bounds__(256) void ln_residual(const float* __restrict__ E,
                                                   const float* __restrict__ A,
                                                   const float* __restrict__ g,
                                                   const float* __restrict__ bb,
                                                   uint32_t* __restrict__ Out) {
    __shared__ float s1[256], s2[256];
    int tid = threadIdx.x;
    size_t base = (size_t)blockIdx.x * 512;
    float2 e = *(const float2*)&E[base + 2 * tid];
    float2 a = *(const float2*)&A[base + 2 * tid];
    float x0 = e.x + a.x, x1 = e.y + a.y;
    s1[tid] = x0 + x1;
    s2[tid] = x0 * x0 + x1 * x1;
    __syncthreads();
    for (int s = 128; s > 0; s >>= 1) {
        if (tid < s) { s1[tid] += s1[tid + s]; s2[tid] += s2[tid + s]; }
        __syncthreads();
    }
    float mu  = s1[0] * (1.0f / 512.0f);
    float var = s2[0] * (1.0f / 512.0f) - mu * mu;
    float inv = rsqrtf(var + 1e-7f);
    float2 gg = *(const float2*)&g[2 * tid];
    float2 bv = *(const float2*)&bb[2 * tid];
    Out[(base >> 1) + tid] = pkh2((x0 - mu) * inv * gg.x + bv.x,
                                  (x1 - mu) * inv * gg.y + bv.y);
}

// =============================================================================
extern "C" void kernel_launch(void* const* d_in, const int* in_sizes, int n_in,
                              void* d_out, int out_size) {
    const float* X    = (const float*)d_in[0];
    const int*   inc  = (const int*)d_in[1];
    const float* E    = (const float*)d_in[3];
    const float* Wqn  = (const float*)d_in[4];   const float* bqn = (const float*)d_in[5];
    const float* Wkn  = (const float*)d_in[6];   const float* bkn = (const float*)d_in[7];
    const float* Wvn  = (const float*)d_in[8];   const float* bvn = (const float*)d_in[9];
    const float* Wqe  = (const float*)d_in[10];  const float* bqe = (const float*)d_in[11];
    const float* Wke  = (const float*)d_in[12];  const float* bke = (const float*)d_in[13];
    const float* Wve  = (const float*)d_in[14];  const float* bve = (const float*)d_in[15];
    const float* Wm1  = (const float*)d_in[16];  const float* bm1 = (const float*)d_in[17];
    const float* Wm2  = (const float*)d_in[18];  const float* bm2 = (const float*)d_in[19];
    const float* g_ln = (const float*)d_in[20];  const float* b_ln = (const float*)d_in[21];

    float* out  = (float*)d_out;
    float* Xout = out;
    float* Eout = out + (size_t)Bc * Nn * Dd;

    float* sc = nullptr;
    cudaGetSymbolAddress((void**)&sc, g_scratch);
    __half*   QnH   = (__half*)(sc + OFF_QNH);
    __half*   KnH   = (__half*)(sc + OFF_KNH);
    __half*   VTnH  = (__half*)(sc + OFF_VTNH);
    __half*   QeH   = (__half*)(sc + OFF_QEH);
    __half*   KeH   = (__half*)(sc + OFF_KEH);
    __half*   VTeH  = (__half*)(sc + OFF_VTEH);
    float*    Eattn = sc + OFF_EATTN;
    uint32_t* Eln   = (uint32_t*)(sc + OFF_ELN);
    uint32_t* Hid   = (uint32_t*)(sc + OFF_HID);
    uint32_t* pkO   = (uint32_t*)(sc + OFF_PKO);
    uint32_t* pkT   = (uint32_t*)(sc + OFF_PKT);
    uint32_t* Xh    = (uint32_t*)(sc + OFF_XH);
    uint32_t* Eh    = (uint32_t*)(sc + OFF_EH);
    __half*   Wt    = (__half*)(sc + OFF_WTH);
    uint32_t* Wtu   = (uint32_t*)(sc + OFF_WTH);
    uint32_t* EoutH = (uint32_t*)(sc + OFF_EOUTH);

    static cudaStream_t sB = nullptr;
    static cudaEvent_t evFork = nullptr, evJoin = nullptr;
    static int attr_set = 0;
    if (!attr_set) {
        cudaFuncSetAttribute(flash_fp16, cudaFuncAttributeMaxDynamicSharedMemorySize,
                             FLASH_SMEM);
        cudaFuncSetAttribute(sgemm_h<128>, cudaFuncAttributeMaxDynamicSharedMemorySize,
                             GEMM_SMEM_128);
        cudaFuncSetAttribute(sgemm_h<64>, cudaFuncAttributeMaxDynamicSharedMemorySize,
                             GEMM_SMEM_64);
        cudaStreamCreateWithFlags(&sB, cudaStreamNonBlocking);
        cudaEventCreateWithFlags(&evFork, cudaEventDisableTiming);
        cudaEventCreateWithFlags(&evJoin, cudaEventDisableTiming);
        attr_set = 1;
    }

    // ---- fork: mask packing + late-needed weight conversion on side stream ----
    cudaEventRecord(evFork, 0);
    cudaStreamWaitEvent(sB, evFork, 0);
    pack_mask<<<(Bc * Nn * (Mm / 32)) / 256, 256, 0, sB>>>(inc, pkO);
    transp_bits<<<1024, 256, 0, sB>>>(pkO, pkT);
    P4 wpB; wpB.p[0] = Wke; wpB.p[1] = Wve; wpB.p[2] = Wm1; wpB.p[3] = Wm2;
    conv_wt4<<<dim3(8, 16, 4), dim3(32, 8), 0, sB>>>(wpB, Wt + 4 * 262144);
    cudaEventRecord(evJoin, sB);

    // ---- main stream: conversions (QKV weights only) -> QKV GEMMs ----
    conv_h2<<<dim3(4096, 2), 256>>>((const float4*)X, (uint2*)Xh, 1048576,
                                    (const float4*)E, (uint2*)Eh, 524288);
    P4 wpA; wpA.p[0] = Wqn; wpA.p[1] = Wkn; wpA.p[2] = Wvn; wpA.p[3] = Wqe;
    conv_wt4<<<dim3(8, 16, 4), dim3(32, 8)>>>(wpA, Wt);

    GemmJobs jobs;
    jobs.j[0] = { Xh, Wtu + 0 * 131072, bqn, QnH,  nullptr, 0, 3, 0, 0, 64 };
    jobs.j[1] = { Xh, Wtu + 1 * 131072, bkn, KnH,  nullptr, 0, 3, 0, 0, 64 };
    jobs.j[2] = { Xh, Wtu + 2 * 131072, bvn, VTnH, nullptr, 0, 4, Nn, 11, 64 };
    jobs.j[3] = { Eh, Wtu + 3 * 131072, bqe, QeH,  nullptr, 0, 3, 0, 0, 32 };
    sgemm_h<128><<<dim3(4, 64, 4), 256, GEMM_SMEM_128>>>(jobs);

    // ---- join: masks + late weights must be ready ----
    cudaStreamWaitEvent(0, evJoin, 0);

    // stage 1: edges attend over nodes
    flash_fp16<<<dim3(Mm / 128, Bc * Hh), 128, FLASH_SMEM>>>(QeH, KnH, VTnH, pkT,
                                                             Eattn, Mm, Nn);

    // residual layernorm + MLP
    ln_residual<<<Bc * Mm, 256>>>(E, Eattn, g_ln, b_ln, Eln);
    jobs.j[0] = { Eln, Wtu + 6 * 131072, bm1, Hid, nullptr, 1, 3, 0, 0, 64 };
    jobs.j[1] = jobs.j[0]; jobs.j[2] = jobs.j[0]; jobs.j[3] = jobs.j[0];
    sgemm_h<64><<<dim3(4, 64, 1), 256, GEMM_SMEM_64>>>(jobs);
    jobs.j[0] = { Hid, Wtu + 7 * 131072, bm2, Eout, EoutH, 0, 2, 0, 0, 64 };
    jobs.j[1] = jobs.j[0]; jobs.j[2] = jobs.j[0]; jobs.j[3] = jobs.j[0];
    sgemm_h<64><<<dim3(4, 64, 1), 256, GEMM_SMEM_64>>>(jobs);

    // edge K/V projections from E_
    jobs.j[0] = { EoutH, Wtu + 4 * 131072, bke, KeH,  nullptr, 0, 3, 0, 0, 64 };
    jobs.j[1] = { EoutH, Wtu + 5 * 131072, bve, VTeH, nullptr, 0, 4, Mm, 10, 64 };
    jobs.j[2] = jobs.j[0]; jobs.j[3] = jobs.j[0];
    sgemm_h<64><<<dim3(4, 64, 2), 256, GEMM_SMEM_64>>>(jobs);

    // stage 2: nodes attend over edges
    flash_fp16<<<dim3(Nn / 128, Bc * Hh), 128, FLASH_SMEM>>>(QnH, KeH, VTeH, pkO,
                                                             Xout, Nn, Mm);
}

// round 17
// speedup vs baseline: 1.0662x; 1.0223x over previous
#include <cuda_runtime.h>
#include <cuda_fp16.h>
#include <math.h>
#include <stdint.h>

#define Bc 4
#define Nn 2048
#define Mm 1024
#define Dd 512
#define Hh 8
#define SCALE 0.125f
#define NEGV -9e15f

// ---------------- scratch (static device memory; no allocations) ------------
#define OFF_QNH   0ULL
#define OFF_KNH   2097152ULL
#define OFF_VTNH  4194304ULL
#define OFF_QEH   6291456ULL
#define OFF_KEH   7340032ULL
#define OFF_VTEH  8388608ULL
#define OFF_EATTN 9437184ULL
#define OFF_ELN   11534336ULL
#define OFF_HID   12582912ULL
#define OFF_PKO   13631488ULL
#define OFF_PKT   13893632ULL
#define OFF_XH    14155776ULL
#define OFF_EH    16252928ULL
#define OFF_WTH   17301504ULL
#define OFF_EOUTH 18350080ULL
#define SCRATCH_FLOATS 19398656ULL

__device__ float g_scratch[SCRATCH_FLOATS];

__device__ __forceinline__ float gelu_exact(float x) {
    return 0.5f * x * (1.0f + erff(x * 0.70710678118654752f));
}

__device__ __forceinline__ uint32_t pkh2(float a, float b) {
    __half2 h = __floats2half2_rn(a, b);
    return *(uint32_t*)&h;
}

__device__ __forceinline__ void mma16(float d[4], const uint32_t a[4],
                                      uint32_t b0, uint32_t b1) {
    asm volatile("mma.sync.aligned.m16n8k16.row.col.f32.f16.f16.f32 "
                 "{%0,%1,%2,%3}, {%4,%5,%6,%7}, {%8,%9}, {%0,%1,%2,%3};"
                 : "+f"(d[0]), "+f"(d[1]), "+f"(d[2]), "+f"(d[3])
                 : "r"(a[0]), "r"(a[1]), "r"(a[2]), "r"(a[3]),
                   "r"(b0), "r"(b1));
}

__device__ __forceinline__ void ldsm4(uint32_t addr, uint32_t& x, uint32_t& y,
                                      uint32_t& z, uint32_t& w) {
    asm volatile("ldmatrix.sync.aligned.m8n8.x4.shared.b16 {%0,%1,%2,%3}, [%4];"
                 : "=r"(x), "=r"(y), "=r"(z), "=r"(w) : "r"(addr));
}

__device__ __forceinline__ void cp16(uint32_t dst, const void* src) {
    asm volatile("cp.async.cg.shared.global [%0], [%1], 16;" :: "r"(dst), "l"(src));
}
#define CP_COMMIT() asm volatile("cp.async.commit_group;")
#define CP_WAIT(n)  asm volatile("cp.async.wait_group %0;" :: "n"(n))

// ---------------- fp16 pre-conversion (fused X + E) ---------------------------
__global__ __launch_bounds__(256) void conv_h2(const float4* __restrict__ inA,
                                               uint2* __restrict__ outA, int nA,
                                               const float4* __restrict__ inB,
                                               uint2* __restrict__ outB, int nB) {
    int i = blockIdx.x * 256 + threadIdx.x;
    const float4* in = (blockIdx.y == 0) ? inA : inB;
    uint2* out = (blockIdx.y == 0) ? outA : outB;
    int n = (blockIdx.y == 0) ? nA : nB;
    if (i < n) {
        float4 v = in[i];
        out[i] = make_uint2(pkh2(v.x, v.y), pkh2(v.z, v.w));
    }
}

// weights: W[k][n] fp32 -> Wt[n][k] half; 64k x 32n tiles, uint32 stores
struct P4 { const float* p[4]; };
__global__ void conv_wt4(P4 ws, __half* __restrict__ out) {
    __shared__ float t[64][33];
    int g = blockIdx.z;
    int k0 = blockIdx.x * 64, n0 = blockIdx.y * 32;
    const float* W = ws.p[g];
    int tx = threadIdx.x, ty = threadIdx.y;   // 32 x 8
#pragma unroll
    for (int i = 0; i < 8; i++)
        t[ty + 8 * i][tx] = W[(size_t)(k0 + ty + 8 * i) * 512 + n0 + tx];
    __syncthreads();
    uint32_t* o = (uint32_t*)(out + (size_t)g * 262144);
#pragma unroll
    for (int i = 0; i < 4; i++) {
        int row = ty + 8 * i;
        o[(((size_t)(n0 + row) * 512 + k0) >> 1) + tx] =
            pkh2(t[2 * tx][row], t[2 * tx + 1][row]);
    }
}

// ---------------- mask pack + bit transpose -----------------------------------
__global__ __launch_bounds__(256) void pack_mask(const int* __restrict__ inc,
                                                 uint32_t* __restrict__ pk) {
    int w = blockIdx.x * 256 + threadIdx.x;
    int row = w >> 5, mw = w & 31;
    const int4* p = (const int4*)(inc + (size_t)row * Mm + mw * 32);
    uint32_t v = 0;
#pragma unroll
    for (int i = 0; i < 8; i++) {
        int4 q = p[i];
        v |= (q.x > 0 ? 1u : 0u) << (i * 4 + 0);
        v |= (q.y > 0 ? 1u : 0u) << (i * 4 + 1);
        v |= (q.z > 0 ? 1u : 0u) << (i * 4 + 2);
        v |= (q.w > 0 ? 1u : 0u) << (i * 4 + 3);
    }
    pk[w] = v;
}

__global__ __launch_bounds__(256) void transp_bits(const uint32_t* __restrict__ pkO,
                                                   uint32_t* __restrict__ pkT) {
    int gw = (blockIdx.x * 256 + threadIdx.x) >> 5;
    int lane = threadIdx.x & 31;
    int b = gw >> 11;
    int rem = gw & 2047;
    int ng = rem >> 5;
    int mw = rem & 31;
    uint32_t w = pkO[((size_t)b * Nn + ng * 32 + lane) * 32 + mw];
    uint32_t o = 0;
#pragma unroll
    for (int j = 0; j < 32; j++) {
        uint32_t bl = __ballot_sync(0xffffffffu, (w >> j) & 1u);
        if (lane == j) o = bl;
    }
    pkT[((size_t)b * Mm + mw * 32 + lane) * 64 + ng] = o;
}

// ---------------- fp16 GEMM: cp.async pipeline + ldmatrix fragments -----------
struct GemmJob {
    const uint32_t* A;
    const uint32_t* W;
    const float*    bias;
    void*           out0;
    void*           out1;
    int act;
    int mode;              // 0 fp32; 2 fp32+half; 3 half; 4 half transposed per head
    int vstride;
    int bshift;
    int nby;
};
struct GemmJobs { GemmJob j[4]; };

#define GEMM_SMEM_128 ((2 * 128 * 36 + 2 * 128 * 36) * 4)
#define GEMM_SMEM_64  ((2 * 64 * 36 + 2 * 128 * 36) * 4)

template <int BM>
__global__ __launch_bounds__(256) void sgemm_h(GemmJobs jobs) {
    const GemmJob J = jobs.j[blockIdx.z];
    if (blockIdx.y >= J.nby) return;

    constexpr int NT = (BM == 128) ? 8 : 4;
    extern __shared__ uint32_t sm[];
    uint32_t* As = sm;
    uint32_t* Ws = sm + 2 * BM * 36;
    uint32_t asAddr = (uint32_t)__cvta_generic_to_shared(As);
    uint32_t wsAddr = (uint32_t)__cvta_generic_to_shared(Ws);

    int tid = threadIdx.x;
    int w = tid >> 5, lane = tid & 31;
    int r = lane >> 2, c = lane & 3;
    int wm = (BM == 128) ? (w & 3) * 32 : (w & 1) * 32;
    int wn = (BM == 128) ? (w >> 2) * 64 : (w >> 1) * 32;
    int row0 = blockIdx.y * BM, col0 = blockIdx.x * 128;

    // ldmatrix lane offsets (u32 units, relative to tile base):
    // A frag (m16k16):  frag0 rows+0 k-lo, frag1 rows+8 k-lo, frag2 rows+0 k-hi, frag3 rows+8 k-hi
    int aoff = ((lane & 7) + ((lane & 8) ? 8 : 0)) * 36 + ((lane & 16) ? 4 : 0);
    // B frags (two n8k16 subtiles): frag0/1 nt-even k-lo/hi, frag2/3 nt-odd k-lo/hi
    int boff = (((lane & 16) ? 8 : 0) + (lane & 7)) * 36 + ((lane & 8) ? 4 : 0);

    float acc[2][NT][4];
#pragma unroll
    for (int mi = 0; mi < 2; mi++)
#pragma unroll
        for (int nt = 0; nt < NT; nt++)
#pragma unroll
            for (int j = 0; j < 4; j++) acc[mi][nt][j] = 0.0f;

    auto stage = [&](int buf, int kc) {
        int kt = kc * 32;
#pragma unroll
        for (int i = 0; i < BM / 32; i++) {
            int lin = tid + i * 256;
            int row = lin >> 3, seg = lin & 7;
            cp16(asAddr + (((buf * BM + row) * 36 + seg * 4) << 2),
                 J.A + (size_t)(row0 + row) * 256 + kt + seg * 4);
        }
#pragma unroll
        for (int i = 0; i < 4; i++) {
            int lin = tid + i * 256;
            int row = lin >> 3, seg = lin & 7;
            cp16(wsAddr + (((buf * 128 + row) * 36 + seg * 4) << 2),
                 J.W + (size_t)(col0 + row) * 256 + kt + seg * 4);
        }
    };

    stage(0, 0);
    CP_COMMIT();

    for (int kc = 0; kc < 8; kc++) {
        if (kc + 1 < 8) {
            stage((kc + 1) & 1, kc + 1);
            CP_COMMIT();
            CP_WAIT(1);
        } else {
            CP_WAIT(0);
        }
        __syncthreads();
        uint32_t ab = asAddr + (((kc & 1) * BM * 36 + wm * 36 + aoff) << 2);
        uint32_t wb = wsAddr + (((kc & 1) * 128 * 36 + wn * 36 + boff) << 2);
#pragma unroll
        for (int ks = 0; ks < 4; ks++) {
            uint32_t a[2][4];
#pragma unroll
            for (int mi = 0; mi < 2; mi++)
                ldsm4(ab + ((mi * 16 * 36 + ks * 8) << 2),
                      a[mi][0], a[mi][1], a[mi][2], a[mi][3]);
#pragma unroll
            for (int ntp = 0; ntp < NT / 2; ntp++) {
                uint32_t b0e, b1e, b0o, b1o;
                ldsm4(wb + ((ntp * 16 * 36 + ks * 8) << 2), b0e, b1e, b0o, b1o);
                mma16(acc[0][2 * ntp],     a[0], b0e, b1e);
                mma16(acc[1][2 * ntp],     a[1], b0e, b1e);
                mma16(acc[0][2 * ntp + 1], a[0], b0o, b1o);
                mma16(acc[1][2 * ntp + 1], a[1], b0o, b1o);
            }
        }
        __syncthreads();
    }

#pragma unroll
    for (int mi = 0; mi < 2; mi++) {
        int row = row0 + wm + mi * 16 + r;
#pragma unroll
        for (int nt = 0; nt < NT; nt++) {
            int col = col0 + wn + nt * 8 + 2 * c;
            float2 bv = *(const float2*)&J.bias[col];
            float x0 = acc[mi][nt][0] + bv.x, y0 = acc[mi][nt][1] + bv.y;
            float x1 = acc[mi][nt][2] + bv.x, y1 = acc[mi][nt][3] + bv.y;
            if (J.act) {
                x0 = gelu_exact(x0); y0 = gelu_exact(y0);
                x1 = gelu_exact(x1); y1 = gelu_exact(y1);
            }
            if (J.mode == 0 || J.mode == 2) {
                float* C = (float*)J.out0;
                *(float2*)&C[(size_t)row * 512 + col] = make_float2(x0, y0);
                *(float2*)&C[(size_t)(row + 8) * 512 + col] = make_float2(x1, y1);
            }
            if (J.mode == 2) {
                uint32_t* Ch = (uint32_t*)J.out1;
                Ch[((size_t)row * 512 + col) >> 1] = pkh2(x0, y0);
                Ch[((size_t)(row + 8) * 512 + col) >> 1] = pkh2(x1, y1);
            }
            if (J.mode == 3) {
                uint32_t* Ch = (uint32_t*)J.out0;
                Ch[((size_t)row * 512 + col) >> 1] = pkh2(x0, y0);
                Ch[((size_t)(row + 8) * 512 + col) >> 1] = pkh2(x1, y1);
            }
            if (J.mode == 4) {
                __half* VT = (__half*)J.out0;
                int h = col >> 6, dd = col & 63;
                int bb = row >> J.bshift;
                int key = row & ((1 << J.bshift) - 1);
                size_t base = ((size_t)(bb * 8 + h) * 64 + dd) * J.vstride;
                size_t base1 = base + J.vstride;
                VT[base + key]      = __float2half_rn(x0);
                VT[base1 + key]     = __float2half_rn(y0);
                VT[base + key + 8]  = __float2half_rn(x1);
                VT[base1 + key + 8] = __float2half_rn(y1);
            }
        }
    }
}

// ---------------- fp16 flash: register P, ldmatrix K/V, 3-deep KV pipe --------
#define KT_ST 2304   /* 64*36 u32 */
#define QS_ST 4608   /* 128*36 u32 */
#define FLASH_SMEM ((6 * KT_ST + QS_ST) * 4)   /* 73728 B */
#define SC2 0.18033688011112042f               /* SCALE * log2(e) */

__global__ __launch_bounds__(128) void flash_fp16(const __half* __restrict__ Q,
                                                  const __half* __restrict__ K,
                                                  const __half* __restrict__ VT,
                                                  const uint32_t* __restrict__ pk,
                                                  float* __restrict__ Out,
                                                  int L1, int L2) {
    extern __shared__ uint32_t fsm[];
    uint32_t* Kt = fsm;                        // [3][64][36]
    uint32_t* Vt = fsm + 3 * KT_ST;            // [3][64][36]
    uint32_t* Qs = fsm + 6 * KT_ST;            // [128][36] Q resident
    uint32_t ktAddr = (uint32_t)__cvta_generic_to_shared(Kt);
    uint32_t vtAddr = (uint32_t)__cvta_generic_to_shared(Vt);
    uint32_t qsAddr = (uint32_t)__cvta_generic_to_shared(Qs);

    int tid = threadIdx.x;
    int w = tid >> 5, lane = tid & 31;
    int r = lane >> 2, c = lane & 3;
    int w32 = w * 32;
    int bh = blockIdx.y;
    int b = bh >> 3, h = bh & 7;
    int q0 = blockIdx.x * 128;

    int soff = (((lane & 16) ? 8 : 0) + (lane & 7)) * 36 + ((lane & 8) ? 4 : 0);

    const __half* Qb  = Q + ((size_t)b * L1 + q0) * 512 + h * 64;
    const __half* Kb  = K + ((size_t)b * L2) * 512 + h * 64;
    const __half* VTb = VT + ((size_t)(b * 8 + h) * 64) * L2;
    int nw = L2 >> 5;
    const uint32_t* pr[2][2];
#pragma unroll
    for (int mi = 0; mi < 2; mi++) {
        pr[mi][0] = pk + ((size_t)b * L1 + q0 + w32 + mi * 16 + r) * nw;
        pr[mi][1] = pk + ((size_t)b * L1 + q0 + w32 + mi * 16 + r + 8) * nw;
    }

    auto stageKV = [&](int buf, int n0) {
#pragma unroll
        for (int i = 0; i < 4; i++) {
            int lin = tid + i * 128;
            int row = lin >> 3, seg = lin & 7;
            cp16(ktAddr + ((buf * KT_ST + row * 36 + seg * 4) << 2),
                 Kb + (size_t)(n0 + row) * 512 + seg * 8);
        }
#pragma unroll
        for (int i = 0; i < 4; i++) {
            int lin = tid + i * 128;
            int row = lin >> 3, seg = lin & 7;
            cp16(vtAddr + ((buf * KT_ST + row * 36 + seg * 4) << 2),
                 VTb + (size_t)row * L2 + n0 + seg * 8);
        }
    };

    int T = L2 >> 6;
#pragma unroll
    for (int i = 0; i < 8; i++) {
        int lin = tid + i * 128;
        int row = lin >> 3, seg = lin & 7;
        cp16(qsAddr + ((row * 36 + seg * 4) << 2),
             Qb + (size_t)row * 512 + seg * 8);
    }
    stageKV(0, 0);
    CP_COMMIT();
    if (T > 1) {
        stageKV(1, 64);
        CP_COMMIT();
    }

    float o[2][8][4];
#pragma unroll
    for (int mi = 0; mi < 2; mi++)
#pragma unroll
        for (int nt = 0; nt < 8; nt++)
#pragma unroll
            for (int j = 0; j < 4; j++) o[mi][nt][j] = 0.0f;
    float mrow[2][2], lrow[2][2];
#pragma unroll
    for (int mi = 0; mi < 2; mi++) {
        mrow[mi][0] = -INFINITY; mrow[mi][1] = -INFINITY;
        lrow[mi][0] = 0.0f; lrow[mi][1] = 0.0f;
    }

    for (int t = 0; t < T; t++) {
        int n0 = t << 6;
        uint32_t mw[2][2][2];
#pragma unroll
        for (int mi = 0; mi < 2; mi++)
#pragma unroll
            for (int hf = 0; hf < 2; hf++) {
                mw[mi][hf][0] = __ldg(pr[mi][hf] + (n0 >> 5));
                mw[mi][hf][1] = __ldg(pr[mi][hf] + (n0 >> 5) + 1);
            }
        if (t + 1 < T) {
            CP_WAIT(1);
        } else {
            CP_WAIT(0);
        }
        __syncthreads();
        if (t + 2 < T) {
            stageKV((t + 2) % 3, (t + 2) << 6);
            CP_COMMIT();
        }
        uint32_t ktb = ktAddr + (((t % 3) * KT_ST + soff) << 2);
        uint32_t vtb = vtAddr + (((t % 3) * KT_ST + soff) << 2);

        // S = Q @ K^T : A from resident Qs (scalar), B via ldmatrix.x4
        float s[2][8][4];
#pragma unroll
        for (int mi = 0; mi < 2; mi++)
#pragma unroll
            for (int nt = 0; nt < 8; nt++)
#pragma unroll
                for (int j = 0; j < 4; j++) s[mi][nt][j] = 0.0f;
#pragma unroll
        for (int ks = 0; ks < 4; ks++) {
            uint32_t a[2][4];
#pragma unroll
            for (int mi = 0; mi < 2; mi++) {
                int mr = w32 + mi * 16;
                a[mi][0] = Qs[(mr + r) * 36 + ks * 8 + c];
                a[mi][1] = Qs[(mr + r + 8) * 36 + ks * 8 + c];
                a[mi][2] = Qs[(mr + r) * 36 + ks * 8 + c + 4];
                a[mi][3] = Qs[(mr + r + 8) * 36 + ks * 8 + c + 4];
            }
#pragma unroll
            for (int ntp = 0; ntp < 4; ntp++) {
                uint32_t b0e, b1e, b0o, b1o;
                ldsm4(ktb + ((ntp * 576 + ks * 8) << 2), b0e, b1e, b0o, b1o);
                mma16(s[0][2 * ntp],     a[0], b0e, b1e);
                mma16(s[1][2 * ntp],     a[1], b0e, b1e);
                mma16(s[0][2 * ntp + 1], a[0], b0o, b1o);
                mma16(s[1][2 * ntp + 1], a[1], b0o, b1o);
            }
        }

        // mask (log2 domain) + online softmax; P packed into registers
        uint32_t pp[2][8][2];
#pragma unroll
        for (int mi = 0; mi < 2; mi++) {
#pragma unroll
            for (int nt = 0; nt < 8; nt++) {
                int k0 = nt * 8 + 2 * c;
                uint32_t wr0 = (k0 < 32) ? mw[mi][0][0] : mw[mi][0][1];
                uint32_t wr1 = (k0 < 32) ? mw[mi][1][0] : mw[mi][1][1];
                int sh = k0 & 31;
                s[mi][nt][0] = ((wr0 >> sh) & 1u)       ? s[mi][nt][0] * SC2 : NEGV;
                s[mi][nt][1] = ((wr0 >> (sh + 1)) & 1u) ? s[mi][nt][1] * SC2 : NEGV;
                s[mi][nt][2] = ((wr1 >> sh) & 1u)       ? s[mi][nt][2] * SC2 : NEGV;
                s[mi][nt][3] = ((wr1 >> (sh + 1)) & 1u) ? s[mi][nt][3] * SC2 : NEGV;
            }

            float tm0 = -INFINITY, tm1 = -INFINITY;
#pragma unroll
            for (int nt = 0; nt < 8; nt++) {
                tm0 = fmaxf(tm0, fmaxf(s[mi][nt][0], s[mi][nt][1]));
                tm1 = fmaxf(tm1, fmaxf(s[mi][nt][2], s[mi][nt][3]));
            }
            tm0 = fmaxf(tm0, __shfl_xor_sync(0xffffffffu, tm0, 1));
            tm0 = fmaxf(tm0, __shfl_xor_sync(0xffffffffu, tm0, 2));
            tm1 = fmaxf(tm1, __shfl_xor_sync(0xffffffffu, tm1, 1));
            tm1 = fmaxf(tm1, __shfl_xor_sync(0xffffffffu, tm1, 2));
            float mn0 = fmaxf(mrow[mi][0], tm0), mn1 = fmaxf(mrow[mi][1], tm1);
            float a0 = exp2f(mrow[mi][0] - mn0), a1 = exp2f(mrow[mi][1] - mn1);
            mrow[mi][0] = mn0; mrow[mi][1] = mn1;

            float rs0 = 0.0f, rs1 = 0.0f;
#pragma unroll
            for (int nt = 0; nt < 8; nt++) {
                float p0 = exp2f(s[mi][nt][0] - mn0);
                float p1 = exp2f(s[mi][nt][1] - mn0);
                float p2 = exp2f(s[mi][nt][2] - mn1);
                float p3 = exp2f(s[mi][nt][3] - mn1);
                rs0 += p0 + p1; rs1 += p2 + p3;
                pp[mi][nt][0] = pkh2(p0, p1);
                pp[mi][nt][1] = pkh2(p2, p3);
            }
            rs0 += __shfl_xor_sync(0xffffffffu, rs0, 1);
            rs0 += __shfl_xor_sync(0xffffffffu, rs0, 2);
            rs1 += __shfl_xor_sync(0xffffffffu, rs1, 1);
            rs1 += __shfl_xor_sync(0xffffffffu, rs1, 2);
            lrow[mi][0] = lrow[mi][0] * a0 + rs0;
            lrow[mi][1] = lrow[mi][1] * a1 + rs1;
#pragma unroll
            for (int nt = 0; nt < 8; nt++) {
                o[mi][nt][0] *= a0; o[mi][nt][1] *= a0;
                o[mi][nt][2] *= a1; o[mi][nt][3] *= a1;
            }
        }

        // O += P @ V : P from registers, V via ldmatrix.x4
#pragma unroll
        for (int kt = 0; kt < 4; kt++) {
            uint32_t pa[2][4];
#pragma unroll
            for (int mi = 0; mi < 2; mi++) {
                pa[mi][0] = pp[mi][2 * kt][0];
                pa[mi][1] = pp[mi][2 * kt][1];
                pa[mi][2] = pp[mi][2 * kt + 1][0];
                pa[mi][3] = pp[mi][2 * kt + 1][1];
            }
#pragma unroll
            for (int ntp = 0; ntp < 4; ntp++) {
                uint32_t b0e, b1e, b0o, b1o;
                ldsm4(vtb + ((ntp * 576 + kt * 8) << 2), b0e, b1e, b0o, b1o);
                mma16(o[0][2 * ntp],     pa[0], b0e, b1e);
                mma16(o[1][2 * ntp],     pa[1], b0e, b1e);
                mma16(o[0][2 * ntp + 1], pa[0], b0o, b1o);
                mma16(o[1][2 * ntp + 1], pa[1], b0o, b1o);
            }
        }
    }

    float* Ob = Out + ((size_t)b * L1 + q0) * 512 + h * 64;
#pragma unroll
    for (int mi = 0; mi < 2; mi++) {
        float inv0 = 1.0f / lrow[mi][0], inv1 = 1.0f / lrow[mi][1];
        int mr = w32 + mi * 16;
#pragma unroll
        for (int nt = 0; nt < 8; nt++) {
            int col = nt * 8 + 2 * c;
            float2 v0, v1;
            v0.x = gelu_exact(o[mi][nt][0] * inv0);
            v0.y = gelu_exact(o[mi][nt][1] * inv0);
            v1.x = gelu_exact(o[mi][nt][2] * inv1);
            v1.y = gelu_exact(o[mi][nt][3] * inv1);
            *(float2*)(Ob + (size_t)(mr + r) * 512 + col) = v0;
            *(float2*)(Ob + (size_t)(mr + r + 8) * 512 + col) = v1;
        }
    }
}

// ---------------- layernorm(E + A) -> half ------------------------------------
__global__ __launch_bounds__(256) void ln_residual(const float* __restrict__ E,
                                                   const float* __restrict__ A,
                                                   const float* __restrict__ g,
                                                   const float* __restrict__ bb,
                                                   uint32_t* __restrict__ Out) {
    __shared__ float s1[256], s2[256];
    int tid = threadIdx.x;
    size_t base = (size_t)blockIdx.x * 512;
    float2 e = *(const float2*)&E[base + 2 * tid];
    float2 a = *(const float2*)&A[base + 2 * tid];
    float x0 = e.x + a.x, x1 = e.y + a.y;
    s1[tid] = x0 + x1;
    s2[tid] = x0 * x0 + x1 * x1;
    __syncthreads();
    for (int s = 128; s > 0; s >>= 1) {
        if (tid < s) { s1[tid] += s1[tid + s]; s2[tid] += s2[tid + s]; }
        __syncthreads();
    }
    float mu  = s1[0] * (1.0f / 512.0f);
    float var = s2[0] * (1.0f / 512.0f) - mu * mu;
    float inv = rsqrtf(var + 1e-7f);
    float2 gg = *(const float2*)&g[2 * tid];
    float2 bv = *(const float2*)&bb[2 * tid];
    Out[(base >> 1) + tid] = pkh2((x0 - mu) * inv * gg.x + bv.x,
                                  (x1 - mu) * inv * gg.y + bv.y);
}

// =============================================================================
extern "C" void kernel_launch(void* const* d_in, const int* in_sizes, int n_in,
                              void* d_out, int out_size) {
    const float* X    = (const float*)d_in[0];
    const int*   inc  = (const int*)d_in[1];
    const float* E    = (const float*)d_in[3];
    const float* Wqn  = (const float*)d_in[4];   const float* bqn = (const float*)d_in[5];
    const float* Wkn  = (const float*)d_in[6];   const float* bkn = (const float*)d_in[7];
    const float* Wvn  = (const float*)d_in[8];   const float* bvn = (const float*)d_in[9];
    const float* Wqe  = (const float*)d_in[10];  const float* bqe = (const float*)d_in[11];
    const float* Wke  = (const float*)d_in[12];  const float* bke = (const float*)d_in[13];
    const float* Wve  = (const float*)d_in[14];  const float* bve = (const float*)d_in[15];
    const float* Wm1  = (const float*)d_in[16];  const float* bm1 = (const float*)d_in[17];
    const float* Wm2  = (const float*)d_in[18];  const float* bm2 = (const float*)d_in[19];
    const float* g_ln = (const float*)d_in[20];  const float* b_ln = (const float*)d_in[21];

    float* out  = (float*)d_out;
    float* Xout = out;
    float* Eout = out + (size_t)Bc * Nn * Dd;

    float* sc = nullptr;
    cudaGetSymbolAddress((void**)&sc, g_scratch);
    __half*   QnH   = (__half*)(sc + OFF_QNH);
    __half*   KnH   = (__half*)(sc + OFF_KNH);
    __half*   VTnH  = (__half*)(sc + OFF_VTNH);
    __half*   QeH   = (__half*)(sc + OFF_QEH);
    __half*   KeH   = (__half*)(sc + OFF_KEH);
    __half*   VTeH  = (__half*)(sc + OFF_VTEH);
    float*    Eattn = sc + OFF_EATTN;
    uint32_t* Eln   = (uint32_t*)(sc + OFF_ELN);
    uint32_t* Hid   = (uint32_t*)(sc + OFF_HID);
    uint32_t* pkO   = (uint32_t*)(sc + OFF_PKO);
    uint32_t* pkT   = (uint32_t*)(sc + OFF_PKT);
    uint32_t* Xh    = (uint32_t*)(sc + OFF_XH);
    uint32_t* Eh    = (uint32_t*)(sc + OFF_EH);
    __half*   Wt    = (__half*)(sc + OFF_WTH);
    uint32_t* Wtu   = (uint32_t*)(sc + OFF_WTH);
    uint32_t* EoutH = (uint32_t*)(sc + OFF_EOUTH);

    static cudaStream_t sB = nullptr;
    static cudaEvent_t evFork = nullptr, evJoin = nullptr;
    static int attr_set = 0;
    if (!attr_set) {
        cudaFuncSetAttribute(flash_fp16, cudaFuncAttributeMaxDynamicSharedMemorySize,
                             FLASH_SMEM);
        cudaFuncSetAttribute(sgemm_h<128>, cudaFuncAttributeMaxDynamicSharedMemorySize,
                             GEMM_SMEM_128);
        cudaFuncSetAttribute(sgemm_h<64>, cudaFuncAttributeMaxDynamicSharedMemorySize,
                             GEMM_SMEM_64);
        cudaStreamCreateWithFlags(&sB, cudaStreamNonBlocking);
        cudaEventCreateWithFlags(&evFork, cudaEventDisableTiming);
        cudaEventCreateWithFlags(&evJoin, cudaEventDisableTiming);
        attr_set = 1;
    }

    // ---- fork: mask packing + late-needed weight conversion on side stream ----
    cudaEventRecord(evFork, 0);
    cudaStreamWaitEvent(sB, evFork, 0);
    pack_mask<<<(Bc * Nn * (Mm / 32)) / 256, 256, 0, sB>>>(inc, pkO);
    transp_bits<<<1024, 256, 0, sB>>>(pkO, pkT);
    P4 wpB; wpB.p[0] = Wke; wpB.p[1] = Wve; wpB.p[2] = Wm1; wpB.p[3] = Wm2;
    conv_wt4<<<dim3(8, 16, 4), dim3(32, 8), 0, sB>>>(wpB, Wt + 4 * 262144);
    cudaEventRecord(evJoin, sB);

    // ---- main stream: conversions (QKV weights only) -> QKV GEMMs ----
    conv_h2<<<dim3(4096, 2), 256>>>((const float4*)X, (uint2*)Xh, 1048576,
                                    (const float4*)E, (uint2*)Eh, 524288);
    P4 wpA; wpA.p[0] = Wqn; wpA.p[1] = Wkn; wpA.p[2] = Wvn; wpA.p[3] = Wqe;
    conv_wt4<<<dim3(8, 16, 4), dim3(32, 8)>>>(wpA, Wt);

    GemmJobs jobs;
    jobs.j[0] = { Xh, Wtu + 0 * 131072, bqn, QnH,  nullptr, 0, 3, 0, 0, 64 };
    jobs.j[1] = { Xh, Wtu + 1 * 131072, bkn, KnH,  nullptr, 0, 3, 0, 0, 64 };
    jobs.j[2] = { Xh, Wtu + 2 * 131072, bvn, VTnH, nullptr, 0, 4, Nn, 11, 64 };
    jobs.j[3] = { Eh, Wtu + 3 * 131072, bqe, QeH,  nullptr, 0, 3, 0, 0, 32 };
    sgemm_h<128><<<dim3(4, 64, 4), 256, GEMM_SMEM_128>>>(jobs);

    // ---- join: masks + late weights must be ready ----
    cudaStreamWaitEvent(0, evJoin, 0);

    // stage 1: edges attend over nodes
    flash_fp16<<<dim3(Mm / 128, Bc * Hh), 128, FLASH_SMEM>>>(QeH, KnH, VTnH, pkT,
                                                             Eattn, Mm, Nn);

    // residual layernorm + MLP
    ln_residual<<<Bc * Mm, 256>>>(E, Eattn, g_ln, b_ln, Eln);
    jobs.j[0] = { Eln, Wtu + 6 * 131072, bm1, Hid, nullptr, 1, 3, 0, 0, 64 };
    jobs.j[1] = jobs.j[0]; jobs.j[2] = jobs.j[0]; jobs.j[3] = jobs.j[0];
    sgemm_h<64><<<dim3(4, 64, 1), 256, GEMM_SMEM_64>>>(jobs);
    jobs.j[0] = { Hid, Wtu + 7 * 131072, bm2, Eout, EoutH, 0, 2, 0, 0, 64 };
    jobs.j[1] = jobs.j[0]; jobs.j[2] = jobs.j[0]; jobs.j[3] = jobs.j[0];
    sgemm_h<64><<<dim3(4, 64, 1), 256, GEMM_SMEM_64>>>(jobs);

    // edge K/V projections from E_
    jobs.j[0] = { EoutH, Wtu + 4 * 131072, bke, KeH,  nullptr, 0, 3, 0, 0, 64 };
    jobs.j[1] = { EoutH, Wtu + 5 * 131072, bve, VTeH, nullptr, 0, 4, Mm, 10, 64 };
    jobs.j[2] = jobs.j[0]; jobs.j[3] = jobs.j[0];
    sgemm_h<64><<<dim3(4, 64, 2), 256, GEMM_SMEM_64>>>(jobs);

    // stage 2: nodes attend over edges
    flash_fp16<<<dim3(Nn / 128, Bc * Hh), 128, FLASH_SMEM>>>(QnH, KeH, VTeH, pkO,
                                                             Xout, Nn, Mm);
}